// round 9
// baseline (speedup 1.0000x reference)
#include <cuda_runtime.h>

// ---------------------------------------------------------------------------
// Problem constants
// ---------------------------------------------------------------------------
#define TT   256          // time frames (h)
#define PP   88           // pitches (w)
#define CC   128          // channels
#define NH   4            // heads
#define HD   32           // head dim
#define WIN  25           // neighborhood window
#define M_ROWS (TT*PP)    // 22528
#define KCAT 144          // padded concat K (128 + 2 + 1 -> pad to 144)
#define BT   8            // t-rows per attention block (4 per ty group)

#define QSCALE 0.17677669529663689f   // 32^-0.5

typedef unsigned long long ull;

// ---- f32x2 packed helpers (sm_103a FFMA2/FADD2 are PTX-only) ---------------
__device__ __forceinline__ ull pk2(float lo, float hi) {
    ull r; asm("mov.b64 %0,{%1,%2};" : "=l"(r) : "f"(lo), "f"(hi)); return r;
}
__device__ __forceinline__ ull dup2(float x) { return pk2(x, x); }
__device__ __forceinline__ ull fma2(ull a, ull b, ull c) {
    ull d; asm("fma.rn.f32x2 %0,%1,%2,%3;" : "=l"(d) : "l"(a), "l"(b), "l"(c)); return d;
}
__device__ __forceinline__ ull add2(ull a, ull b) {
    ull d; asm("add.rn.f32x2 %0,%1,%2;" : "=l"(d) : "l"(a), "l"(b)); return d;
}
__device__ __forceinline__ void upk2(ull v, float& lo, float& hi) {
    asm("mov.b64 {%0,%1},%2;" : "=f"(lo), "=f"(hi) : "l"(v));
}

// ---------------------------------------------------------------------------
// Scratch (static device globals -- no allocation allowed)
// ---------------------------------------------------------------------------
__device__ float g_Y[M_ROWS * CC];
__device__ float g_QKV[3 * NH * M_ROWS * HD];   // [i3][head][m][hd]
__device__ float g_AO[M_ROWS * CC];
__device__ float g_WtLin[KCAT * CC];            // [k][n]
__device__ float g_WtQkv[CC * 3 * CC];          // [k][n] n<384
__device__ float g_WtProj[CC * CC];             // [k][n]

// ---------------------------------------------------------------------------
// Prep kernel: transpose weights to [k][n], zero-pad k
// ---------------------------------------------------------------------------
__global__ void transpose_w_kernel(float* __restrict__ dst, const float* __restrict__ src,
                                   int Ksrc, int Kdst, int N) {
    int idx = blockIdx.x * 256 + threadIdx.x;
    if (idx >= Kdst * N) return;
    int k = idx / N, n = idx - k * N;
    dst[idx] = (k < Ksrc) ? src[n * Ksrc + k] : 0.f;
}

// ---------------------------------------------------------------------------
// Tiled SGEMM with f32x2 FMAs:  C[m][n] = sum_k A[m][k] * Bt[k][n] + bias[n]
// BM = BN = 128, BK = 16, 256 threads, 8x8 micro-tile (held as 8x4 f32x2).
// MODE 0: fusion  (A is the virtual concat [x | cond | mask | 0-pad], relu)
// MODE 1: qkv     (scatter into g_QKV layout, scale q by HD^-0.5)
// MODE 2: proj    (write row-major CC)
// ---------------------------------------------------------------------------
template <int MODE>
__global__ void __launch_bounds__(256) gemm_kernel(const float* __restrict__ A, int lda,
                                                   const float* __restrict__ Bt, int ldb,
                                                   const float* __restrict__ bias,
                                                   float* __restrict__ C, int K,
                                                   const float* __restrict__ cond,
                                                   const float* __restrict__ maskp) {
    __shared__ float As[16][132];   // [k][m], padded
    __shared__ float Bs[16][128];   // [k][n]

    const int m0 = blockIdx.y * 128;
    const int n0 = blockIdx.x * 128;
    const int tid = threadIdx.x;
    const int tx = tid & 15;
    const int ty = tid >> 4;

    ull acc2[8][4];
#pragma unroll
    for (int i = 0; i < 8; i++)
#pragma unroll
        for (int j = 0; j < 4; j++) acc2[i][j] = 0ull;

    for (int k0 = 0; k0 < K; k0 += 16) {
#pragma unroll
        for (int ii = 0; ii < 2; ii++) {
            int lin = tid + ii * 256;
            int r  = lin >> 2;            // 0..127
            int c4 = (lin & 3) * 4;       // 0,4,8,12
            int row = m0 + r;
            float4 a4;
            if (MODE == 0) {
                // virtual concat row: [x(128) | cond(2) | mask(1) | zeros]
                if (k0 < CC) {
                    a4 = *(const float4*)(A + row * CC + k0 + c4);
                } else if (c4 == 0) {
                    a4 = make_float4(cond[row * 2], cond[row * 2 + 1], maskp[row], 0.f);
                } else {
                    a4 = make_float4(0.f, 0.f, 0.f, 0.f);
                }
            } else {
                a4 = *(const float4*)(A + row * lda + k0 + c4);
            }
            As[c4 + 0][r] = a4.x; As[c4 + 1][r] = a4.y;
            As[c4 + 2][r] = a4.z; As[c4 + 3][r] = a4.w;
            int rb = lin >> 5;            // 0..15
            int cb = (lin & 31) * 4;      // 0..124
            *(float4*)&Bs[rb][cb] = *(const float4*)(Bt + (k0 + rb) * ldb + n0 + cb);
        }
        __syncthreads();
#pragma unroll
        for (int kk = 0; kk < 16; kk++) {
            float a[8];
            *(float4*)&a[0] = *(const float4*)&As[kk][ty * 8];
            *(float4*)&a[4] = *(const float4*)&As[kk][ty * 8 + 4];
            const ull* bp = (const ull*)&Bs[kk][tx * 8];
            ull b2[4] = { bp[0], bp[1], bp[2], bp[3] };
#pragma unroll
            for (int i = 0; i < 8; i++) {
                ull ad = dup2(a[i]);
#pragma unroll
                for (int j = 0; j < 4; j++)
                    acc2[i][j] = fma2(ad, b2[j], acc2[i][j]);
            }
        }
        __syncthreads();
    }

    // epilogue
#pragma unroll
    for (int i = 0; i < 8; i++) {
        int m = m0 + ty * 8 + i;
#pragma unroll
        for (int j4 = 0; j4 < 2; j4++) {
            int nbase = n0 + tx * 8 + j4 * 4;
            float vv[4];
            upk2(acc2[i][j4 * 2 + 0], vv[0], vv[1]);
            upk2(acc2[i][j4 * 2 + 1], vv[2], vv[3]);
#pragma unroll
            for (int j = 0; j < 4; j++) {
                float t = vv[j] + bias[nbase + j];
                if (MODE == 0) t = fmaxf(t, 0.f);
                if (MODE == 1 && nbase < 128) t *= QSCALE;
                vv[j] = t;
            }
            if (MODE == 1) {
                int i3   = nbase >> 7;
                int head = (nbase >> 5) & 3;
                int hd   = nbase & 31;
                *(float4*)&C[((i3 * NH + head) * M_ROWS + m) * HD + hd] = *(float4*)vv;
            } else {
                *(float4*)&C[m * CC + nbase] = *(float4*)vv;
            }
        }
    }
}

// ---------------------------------------------------------------------------
// Neighborhood attention: one head per block, BT=8 t-rows, 176 threads (88 p
// x 2 ty). Each thread owns FOUR t-consecutive queries (t0+4*ty+i, p): every
// K/V LDS.64 feeds 4 fma2 -> half the smem bytes/query of the 2q scheme.
// Max-free softmax (scores tiny). Window slab [x0, x0+25] = 13 f32x2 pairs,
// processed in two jp-halves (7+6) to cap live packed-score registers at 56
// while o[4][32] stays scalar-resident. l accumulated packed (l2), reduced
// once at the end. Full 176-thread blocks: no dead lanes, occ 1 (regs ~245).
// ---------------------------------------------------------------------------
__global__ void __launch_bounds__(176, 1) attn_kernel(const float* __restrict__ QKVbuf,
                                                      const float* __restrict__ rpb,
                                                      float* __restrict__ AO) {
    __shared__ float Ksh[HD][90];   // [d][p], 8B-aligned rows, conflict-free
    __shared__ float Vsh[HD][90];
    __shared__ float Rpb[49 * 49];

    const int h  = blockIdx.y;
    const int t0 = blockIdx.x * BT;
    const int p  = threadIdx.x;          // 0..87
    const int ty = threadIdx.y;          // 0..1
    const int tid = ty * PP + p;         // 0..175

    const float* Qg = QKVbuf;
    const float* Kg = QKVbuf + NH * M_ROWS * HD;
    const float* Vg = QKVbuf + 2 * NH * M_ROWS * HD;

    for (int i = tid; i < 49 * 49; i += 176) Rpb[i] = rpb[h * 49 * 49 + i];

    const int tq0 = t0 + ty * 4;         // this thread's 4 query rows: tq0..tq0+3
    int s_[4];
#pragma unroll
    for (int i = 0; i < 4; i++) s_[i] = min(max(tq0 + i - 12, 0), TT - WIN);

    const int pw0 = min(max(p - 12, 0), PP - WIN);
    const int x0  = pw0 & ~1;            // even slab base
    const bool ok0  = (pw0 == x0);       // slot 0 valid iff slab unshifted
    const bool ok25 = (pw0 != x0);       // slot 25 valid iff slab shifted
    const int rwb = x0 - p + 24;         // rpb col for slot 0

    const float* qp = Qg + ((h * TT + tq0) * PP + p) * HD;  // query i at +i*PP*HD

    float o[4][HD];
#pragma unroll
    for (int i = 0; i < 4; i++)
#pragma unroll
        for (int d = 0; d < HD; d++) o[i][d] = 0.f;
    ull l2[4] = {0ull, 0ull, 0ull, 0ull};

    const int rlo = min(max(t0 - 12, 0), TT - WIN);
    const int rhi = min(max(t0 + BT - 1 - 12, 0), TT - WIN) + WIN - 1;

    for (int tr = rlo; tr <= rhi; tr++) {
        __syncthreads();                 // prior compute done reading smem
        // cooperative load of key/value t-row tr, transposed to [d][p]
        const float* kb = Kg + (h * TT + tr) * PP * HD;
        const float* vb = Vg + (h * TT + tr) * PP * HD;
#pragma unroll
        for (int it = 0; it < 4; it++) {
            int e  = tid + it * 176;     // 0..703 (= PP*8)
            int pc = e >> 3;
            int dq = (e & 7) * 4;
            float4 k4 = *(const float4*)(kb + pc * HD + dq);
            float4 v4 = *(const float4*)(vb + pc * HD + dq);
            Ksh[dq + 0][pc] = k4.x; Ksh[dq + 1][pc] = k4.y;
            Ksh[dq + 2][pc] = k4.z; Ksh[dq + 3][pc] = k4.w;
            Vsh[dq + 0][pc] = v4.x; Vsh[dq + 1][pc] = v4.y;
            Vsh[dq + 2][pc] = v4.z; Vsh[dq + 3][pc] = v4.w;
        }
        __syncthreads();                 // smem row tr visible

        bool act[4]; bool any = false;
#pragma unroll
        for (int i = 0; i < 4; i++) {
            act[i] = (tr >= s_[i]) && (tr < s_[i] + WIN);
            any = any || act[i];
        }
        if (!any) continue;

#pragma unroll
        for (int half = 0; half < 2; half++) {
            const int jb = half ? 7 : 0;       // pair-index base
            const int jn = half ? 6 : 7;       // pairs this half

            // ---- scores: s2[i][jp] = (q_i . K[:, x0+2(jb+jp)], q_i . K[:, ..+1])
            ull s2[4][7];
#pragma unroll
            for (int i = 0; i < 4; i++)
#pragma unroll
                for (int jp = 0; jp < 7; jp++) s2[i][jp] = 0ull;

#pragma unroll
            for (int d4 = 0; d4 < HD / 4; d4++) {
                float4 q4[4];
#pragma unroll
                for (int i = 0; i < 4; i++)
                    q4[i] = *(const float4*)(qp + i * PP * HD + d4 * 4);
#pragma unroll
                for (int dd = 0; dd < 4; dd++) {
                    const int d = d4 * 4 + dd;
                    ull qd[4];
                    qd[0] = dup2(((const float*)&q4[0])[dd]);
                    qd[1] = dup2(((const float*)&q4[1])[dd]);
                    qd[2] = dup2(((const float*)&q4[2])[dd]);
                    qd[3] = dup2(((const float*)&q4[3])[dd]);
                    const ull* kr = (const ull*)&Ksh[d][x0] + jb;
#pragma unroll
                    for (int jp = 0; jp < 7; jp++) {
                        if (jp >= jn) break;
                        ull k2 = kr[jp];
#pragma unroll
                        for (int i = 0; i < 4; i++)
                            s2[i][jp] = fma2(qd[i], k2, s2[i][jp]);
                    }
                }
            }

            // ---- + rpb, exp (max-free, MUFU pipe), packed l accumulate
#pragma unroll
            for (int i = 0; i < 4; i++) {
                if (act[i]) {
                    const int base = (tr - (tq0 + i) + 24) * 49 + rwb;
#pragma unroll
                    for (int jp = 0; jp < 7; jp++) {
                        if (jp >= jn) break;
                        const int s0 = 2 * (jb + jp), s1 = s0 + 1;
                        float f0, f1;
                        upk2(s2[i][jp], f0, f1);
                        float g0 = (s0 != 0  || ok0)  ? __expf(f0 + Rpb[base + s0]) : 0.f;
                        float g1 = (s1 != 25 || ok25) ? __expf(f1 + Rpb[base + s1]) : 0.f;
                        ull e2 = pk2(g0, g1);
                        l2[i] = add2(l2[i], e2);
                        s2[i][jp] = e2;
                    }
                } else {
#pragma unroll
                    for (int jp = 0; jp < 7; jp++) s2[i][jp] = 0ull;
                }
            }

            // ---- AV accumulate (each V LDS.64 feeds 4 fma2)
#pragma unroll
            for (int d = 0; d < HD; d++) {
                const ull* vr = (const ull*)&Vsh[d][x0] + jb;
                ull acc[4] = {0ull, 0ull, 0ull, 0ull};
#pragma unroll
                for (int jp = 0; jp < 7; jp++) {
                    if (jp >= jn) break;
                    ull v2 = vr[jp];
#pragma unroll
                    for (int i = 0; i < 4; i++)
                        acc[i] = fma2(s2[i][jp], v2, acc[i]);
                }
#pragma unroll
                for (int i = 0; i < 4; i++) {
                    float lo, hi;
                    upk2(acc[i], lo, hi);
                    o[i][d] += lo + hi;
                }
            }
        }
    }

#pragma unroll
    for (int i = 0; i < 4; i++) {
        float lo, hi;
        upk2(l2[i], lo, hi);
        const float inv = 1.f / (lo + hi);
        float* outp = AO + ((tq0 + i) * PP + p) * CC + h * HD;
#pragma unroll
        for (int d4 = 0; d4 < HD / 4; d4++) {
            float4 v = make_float4(o[i][d4*4] * inv, o[i][d4*4+1] * inv,
                                   o[i][d4*4+2] * inv, o[i][d4*4+3] * inv);
            *(float4*)(outp + d4 * 4) = v;
        }
    }
}

// ---------------------------------------------------------------------------
// Launch
// ---------------------------------------------------------------------------
extern "C" void kernel_launch(void* const* d_in, const int* in_sizes, int n_in,
                              void* d_out, int out_size) {
    const float* x      = (const float*)d_in[0];
    const float* cond   = (const float*)d_in[1];
    const float* mask   = (const float*)d_in[2];
    const float* lin_w  = (const float*)d_in[3];
    const float* lin_b  = (const float*)d_in[4];
    const float* qkv_w  = (const float*)d_in[5];
    const float* qkv_b  = (const float*)d_in[6];
    const float* rpb    = (const float*)d_in[7];
    const float* proj_w = (const float*)d_in[8];
    const float* proj_b = (const float*)d_in[9];
    float* out = (float*)d_out;

    float *pY, *pQKV, *pAO, *pWtLin, *pWtQkv, *pWtProj;
    cudaGetSymbolAddress((void**)&pY,      g_Y);
    cudaGetSymbolAddress((void**)&pQKV,    g_QKV);
    cudaGetSymbolAddress((void**)&pAO,     g_AO);
    cudaGetSymbolAddress((void**)&pWtLin,  g_WtLin);
    cudaGetSymbolAddress((void**)&pWtQkv,  g_WtQkv);
    cudaGetSymbolAddress((void**)&pWtProj, g_WtProj);

    // weight transposes
    transpose_w_kernel<<<(KCAT * CC + 255) / 256, 256>>>(pWtLin, lin_w, 131, KCAT, CC);
    transpose_w_kernel<<<(CC * 384 + 255) / 256, 256>>>(pWtQkv, qkv_w, CC, CC, 384);
    transpose_w_kernel<<<(CC * CC + 255) / 256, 256>>>(pWtProj, proj_w, CC, CC, CC);

    // fusion linear + relu -> Y  (concat fused into the A-tile load)
    gemm_kernel<0><<<dim3(1, M_ROWS / 128), 256>>>(x, CC, pWtLin, CC, lin_b, pY, KCAT,
                                                   cond, mask);

    for (int layer = 0; layer < 2; layer++) {
        // QKV projection (scatter into per-head layout, q pre-scaled)
        gemm_kernel<1><<<dim3(3, M_ROWS / 128), 256>>>(pY, CC, pWtQkv, 384, qkv_b, pQKV, CC,
                                                       nullptr, nullptr);
        // neighborhood attention -> AO (merged-head layout)
        attn_kernel<<<dim3(TT / BT, NH), dim3(PP, 2)>>>(pQKV, rpb, pAO);
        // output projection
        float* dst = (layer == 0) ? pY : out;
        gemm_kernel<2><<<dim3(1, M_ROWS / 128), 256>>>(pAO, CC, pWtProj, CC, proj_b, dst, CC,
                                                       nullptr, nullptr);
    }
}

// round 10
// speedup vs baseline: 1.3172x; 1.3172x over previous
#include <cuda_runtime.h>

// ---------------------------------------------------------------------------
// Problem constants
// ---------------------------------------------------------------------------
#define TT   256          // time frames (h)
#define PP   88           // pitches (w)
#define CC   128          // channels
#define NH   4            // heads
#define HD   32           // head dim
#define WIN  25           // neighborhood window
#define M_ROWS (TT*PP)    // 22528
#define KCAT 144          // padded concat K (128 + 2 + 1 -> pad to 144)
#define BT   4            // t-rows per attention block

#define QSCALE 0.17677669529663689f   // 32^-0.5
#define KVS    92                     // K/V smem row stride (floats, 16B-aligned)

typedef unsigned long long ull;

// ---- f32x2 packed helpers (sm_103a FFMA2/FADD2 are PTX-only) ---------------
__device__ __forceinline__ ull pk2(float lo, float hi) {
    ull r; asm("mov.b64 %0,{%1,%2};" : "=l"(r) : "f"(lo), "f"(hi)); return r;
}
__device__ __forceinline__ ull dup2(float x) { return pk2(x, x); }
__device__ __forceinline__ ull fma2(ull a, ull b, ull c) {
    ull d; asm("fma.rn.f32x2 %0,%1,%2,%3;" : "=l"(d) : "l"(a), "l"(b), "l"(c)); return d;
}
__device__ __forceinline__ ull add2(ull a, ull b) {
    ull d; asm("add.rn.f32x2 %0,%1,%2;" : "=l"(d) : "l"(a), "l"(b)); return d;
}
__device__ __forceinline__ void upk2(ull v, float& lo, float& hi) {
    asm("mov.b64 {%0,%1},%2;" : "=f"(lo), "=f"(hi) : "l"(v));
}

// ---------------------------------------------------------------------------
// Scratch (static device globals -- no allocation allowed)
// ---------------------------------------------------------------------------
__device__ float g_Y[M_ROWS * CC];
__device__ float g_QKV[3 * NH * M_ROWS * HD];   // [i3][head][m][hd]
__device__ float g_AO[M_ROWS * CC];
__device__ float g_WtLin[KCAT * CC];            // [k][n]
__device__ float g_WtQkv[CC * 3 * CC];          // [k][n] n<384
__device__ float g_WtProj[CC * CC];             // [k][n]

// ---------------------------------------------------------------------------
// Prep kernel: transpose weights to [k][n], zero-pad k
// ---------------------------------------------------------------------------
__global__ void transpose_w_kernel(float* __restrict__ dst, const float* __restrict__ src,
                                   int Ksrc, int Kdst, int N) {
    int idx = blockIdx.x * 256 + threadIdx.x;
    if (idx >= Kdst * N) return;
    int k = idx / N, n = idx - k * N;
    dst[idx] = (k < Ksrc) ? src[n * Ksrc + k] : 0.f;
}

// ---------------------------------------------------------------------------
// Tiled SGEMM with f32x2 FMAs:  C[m][n] = sum_k A[m][k] * Bt[k][n] + bias[n]
// BM = BN = 128, BK = 16, 256 threads, 8x8 micro-tile (held as 8x4 f32x2).
// MODE 0: fusion  (A is the virtual concat [x | cond | mask | 0-pad], relu)
// MODE 1: qkv     (scatter into g_QKV layout, scale q by HD^-0.5)
// MODE 2: proj    (write row-major CC)
// ---------------------------------------------------------------------------
template <int MODE>
__global__ void __launch_bounds__(256) gemm_kernel(const float* __restrict__ A, int lda,
                                                   const float* __restrict__ Bt, int ldb,
                                                   const float* __restrict__ bias,
                                                   float* __restrict__ C, int K,
                                                   const float* __restrict__ cond,
                                                   const float* __restrict__ maskp) {
    __shared__ float As[16][132];   // [k][m], padded
    __shared__ float Bs[16][128];   // [k][n]

    const int m0 = blockIdx.y * 128;
    const int n0 = blockIdx.x * 128;
    const int tid = threadIdx.x;
    const int tx = tid & 15;
    const int ty = tid >> 4;

    ull acc2[8][4];
#pragma unroll
    for (int i = 0; i < 8; i++)
#pragma unroll
        for (int j = 0; j < 4; j++) acc2[i][j] = 0ull;

    for (int k0 = 0; k0 < K; k0 += 16) {
#pragma unroll
        for (int ii = 0; ii < 2; ii++) {
            int lin = tid + ii * 256;
            int r  = lin >> 2;            // 0..127
            int c4 = (lin & 3) * 4;       // 0,4,8,12
            int row = m0 + r;
            float4 a4;
            if (MODE == 0) {
                // virtual concat row: [x(128) | cond(2) | mask(1) | zeros]
                if (k0 < CC) {
                    a4 = *(const float4*)(A + row * CC + k0 + c4);
                } else if (c4 == 0) {
                    a4 = make_float4(cond[row * 2], cond[row * 2 + 1], maskp[row], 0.f);
                } else {
                    a4 = make_float4(0.f, 0.f, 0.f, 0.f);
                }
            } else {
                a4 = *(const float4*)(A + row * lda + k0 + c4);
            }
            As[c4 + 0][r] = a4.x; As[c4 + 1][r] = a4.y;
            As[c4 + 2][r] = a4.z; As[c4 + 3][r] = a4.w;
            int rb = lin >> 5;            // 0..15
            int cb = (lin & 31) * 4;      // 0..124
            *(float4*)&Bs[rb][cb] = *(const float4*)(Bt + (k0 + rb) * ldb + n0 + cb);
        }
        __syncthreads();
#pragma unroll
        for (int kk = 0; kk < 16; kk++) {
            float a[8];
            *(float4*)&a[0] = *(const float4*)&As[kk][ty * 8];
            *(float4*)&a[4] = *(const float4*)&As[kk][ty * 8 + 4];
            const ull* bp = (const ull*)&Bs[kk][tx * 8];
            ull b2[4] = { bp[0], bp[1], bp[2], bp[3] };
#pragma unroll
            for (int i = 0; i < 8; i++) {
                ull ad = dup2(a[i]);
#pragma unroll
                for (int j = 0; j < 4; j++)
                    acc2[i][j] = fma2(ad, b2[j], acc2[i][j]);
            }
        }
        __syncthreads();
    }

    // epilogue
#pragma unroll
    for (int i = 0; i < 8; i++) {
        int m = m0 + ty * 8 + i;
#pragma unroll
        for (int j4 = 0; j4 < 2; j4++) {
            int nbase = n0 + tx * 8 + j4 * 4;
            float vv[4];
            upk2(acc2[i][j4 * 2 + 0], vv[0], vv[1]);
            upk2(acc2[i][j4 * 2 + 1], vv[2], vv[3]);
#pragma unroll
            for (int j = 0; j < 4; j++) {
                float t = vv[j] + bias[nbase + j];
                if (MODE == 0) t = fmaxf(t, 0.f);
                if (MODE == 1 && nbase < 128) t *= QSCALE;
                vv[j] = t;
            }
            if (MODE == 1) {
                int i3   = nbase >> 7;
                int head = (nbase >> 5) & 3;
                int hd   = nbase & 31;
                *(float4*)&C[((i3 * NH + head) * M_ROWS + m) * HD + hd] = *(float4*)vv;
            } else {
                *(float4*)&C[m * CC + nbase] = *(float4*)vv;
            }
        }
    }
}

// ---------------------------------------------------------------------------
// Neighborhood attention: one head per block, BT=4 t-rows, 176 threads, each
// thread owns 2 t-packed queries (ta=t0+ty, tb=ta+2) -- the proven structure.
// NEW vs R8:
//  * K/V smem reads via LDS.128 over a 16B-aligned 28-col slab [x4, x4+28):
//    4 adjacent lanes share each 16B chunk -> every warp LDS.128 dedups to
//    128B = 1 cyc. Crossbar cycles AND LDS instruction count HALVE.
//  * Transposed STS with (pc = tid%88, dq = (tid/88 + 2*it)*4) mapping:
//    within-warp banks = pc mod 32 -> conflict-free (old mapping was 4-way).
//  * Slab masking: slots j in {0,1,2,25,26,27} predicated on c0 = pw0-x4.
//  * Packed l2 accumulation; max-free softmax (scores tiny, no overflow).
// ---------------------------------------------------------------------------
__global__ void __launch_bounds__(176, 2) attn_kernel(const float* __restrict__ QKVbuf,
                                                      const float* __restrict__ rpb,
                                                      float* __restrict__ AO) {
    __shared__ float Ksh[HD][KVS];   // [d][p], 368B rows (16B-aligned)
    __shared__ float Vsh[HD][KVS];
    __shared__ float Rpb[4 + 49 * 49 + 8];   // padded both ends for slab reads

    const int h  = blockIdx.y;
    const int t0 = blockIdx.x * BT;
    const int p  = threadIdx.x;          // 0..87
    const int ty = threadIdx.y;          // 0..1
    const int tid = ty * PP + p;         // 0..175

    const float* Qg = QKVbuf;
    const float* Kg = QKVbuf + NH * M_ROWS * HD;
    const float* Vg = QKVbuf + 2 * NH * M_ROWS * HD;

    for (int i = tid; i < 4 + 49 * 49 + 8; i += 176)
        Rpb[i] = (i >= 4 && i < 4 + 2401) ? rpb[h * 2401 + (i - 4)] : 0.f;

    const int ta  = t0 + ty;             // query rows: ta, ta+2
    const int tb  = ta + 2;
    const int sa  = min(max(ta - 12, 0), TT - WIN);
    const int sb  = min(max(tb - 12, 0), TT - WIN);
    const int pw0 = min(max(p - 12, 0), PP - WIN);
    const int x4  = pw0 & ~3;            // 16B-aligned slab base
    const int c0  = pw0 - x4;            // 0..3 : window = slots [c0, c0+25)
    // slot validity (slots 3..24 always valid)
    const bool v0  = (c0 == 0);
    const bool v1  = (c0 <= 1);
    const bool v2  = (c0 <= 2);
    const bool v25 = (c0 >= 1);
    const bool v26 = (c0 >= 2);
    const bool v27 = (c0 == 3);
    const int rwb = x4 - p + 24;         // rpb col for slot 0

    const float4* qa_ptr = (const float4*)(Qg + ((h * TT + ta) * PP + p) * HD);
    const float4* qb_ptr = (const float4*)(Qg + ((h * TT + tb) * PP + p) * HD);

    float oA[HD], oB[HD];
#pragma unroll
    for (int d = 0; d < HD; d++) { oA[d] = 0.f; oB[d] = 0.f; }
    ull la2 = 0ull, lb2 = 0ull;

    const int rlo = min(max(t0 - 12, 0), TT - WIN);
    const int rhi = min(max(t0 + BT - 1 - 12, 0), TT - WIN) + WIN - 1;

    const int pL = p;                    // tid % 88
    const int g0 = ty;                   // tid / 88

    for (int tr = rlo; tr <= rhi; tr++) {
        __syncthreads();                 // prior compute done reading smem
        // cooperative load of key/value t-row tr, transposed to [d][p]
        // lane pL loads K[pL][dq..dq+3]; STS banks = pL mod 32 -> conflict-free
        const float* kb = Kg + (h * TT + tr) * PP * HD + pL * HD;
        const float* vb = Vg + (h * TT + tr) * PP * HD + pL * HD;
#pragma unroll
        for (int it = 0; it < 4; it++) {
            const int dq = (g0 + 2 * it) * 4;        // 0,8,16,24 / 4,12,20,28
            float4 k4 = *(const float4*)(kb + dq);
            float4 v4 = *(const float4*)(vb + dq);
            Ksh[dq + 0][pL] = k4.x; Ksh[dq + 1][pL] = k4.y;
            Ksh[dq + 2][pL] = k4.z; Ksh[dq + 3][pL] = k4.w;
            Vsh[dq + 0][pL] = v4.x; Vsh[dq + 1][pL] = v4.y;
            Vsh[dq + 2][pL] = v4.z; Vsh[dq + 3][pL] = v4.w;
        }
        __syncthreads();                 // smem row tr visible

        const bool actA = (tr >= sa) && (tr < sa + WIN);
        const bool actB = (tr >= sb) && (tr < sb + WIN);
        if (!(actA || actB)) continue;

        // ---- scores: sX2[jp] = (q . K[:, x4+2jp], q . K[:, x4+2jp+1]), jp<14
        ull sA2[14], sB2[14];
#pragma unroll
        for (int jp = 0; jp < 14; jp++) { sA2[jp] = 0ull; sB2[jp] = 0ull; }

#pragma unroll
        for (int d4 = 0; d4 < HD / 4; d4++) {
            float4 qa4 = qa_ptr[d4];
            float4 qb4 = qb_ptr[d4];
            const float* qaf = (const float*)&qa4;
            const float* qbf = (const float*)&qb4;
#pragma unroll
            for (int dd = 0; dd < 4; dd++) {
                const int d = d4 * 4 + dd;
                ull qaD = dup2(qaf[dd]);
                ull qbD = dup2(qbf[dd]);
                const float4* kr4 = (const float4*)&Ksh[d][x4];
#pragma unroll
                for (int jq = 0; jq < 7; jq++) {     // 7 x LDS.128
                    float4 kv = kr4[jq];
                    const ull* kp = (const ull*)&kv;
                    sA2[2*jq+0] = fma2(qaD, kp[0], sA2[2*jq+0]);
                    sA2[2*jq+1] = fma2(qaD, kp[1], sA2[2*jq+1]);
                    sB2[2*jq+0] = fma2(qbD, kp[0], sB2[2*jq+0]);
                    sB2[2*jq+1] = fma2(qbD, kp[1], sB2[2*jq+1]);
                }
            }
        }

        // ---- + rpb, exp (max-free), packed l accumulate; repack probs
        const int baseA = 4 + (tr - ta + 24) * 49 + rwb;
        const int baseB = 4 + (tr - tb + 24) * 49 + rwb;
#pragma unroll
        for (int jp = 0; jp < 14; jp++) {
            const int s0 = 2 * jp, s1 = 2 * jp + 1;
            const bool ok0 = (s0 == 0) ? v0 : (s0 == 2) ? v2 : (s0 == 26) ? v26 : true;
            const bool ok1 = (s1 == 1) ? v1 : (s1 == 25) ? v25 : (s1 == 27) ? v27 : true;
            float f0, f1, g0f, g1f;
            upk2(sA2[jp], f0, f1);
            g0f = (actA && ok0) ? __expf(f0 + Rpb[baseA + s0]) : 0.f;
            g1f = (actA && ok1) ? __expf(f1 + Rpb[baseA + s1]) : 0.f;
            ull eA = pk2(g0f, g1f);
            la2 = add2(la2, eA);
            sA2[jp] = eA;
            upk2(sB2[jp], f0, f1);
            g0f = (actB && ok0) ? __expf(f0 + Rpb[baseB + s0]) : 0.f;
            g1f = (actB && ok1) ? __expf(f1 + Rpb[baseB + s1]) : 0.f;
            ull eB = pk2(g0f, g1f);
            lb2 = add2(lb2, eB);
            sB2[jp] = eB;
        }

        // ---- AV accumulate (7 x LDS.128 per d, shared by both queries)
#pragma unroll
        for (int d = 0; d < HD; d++) {
            const float4* vr4 = (const float4*)&Vsh[d][x4];
            ull aA = 0ull, aB = 0ull;
#pragma unroll
            for (int jq = 0; jq < 7; jq++) {
                float4 vv = vr4[jq];
                const ull* vp = (const ull*)&vv;
                aA = fma2(sA2[2*jq+0], vp[0], aA);
                aA = fma2(sA2[2*jq+1], vp[1], aA);
                aB = fma2(sB2[2*jq+0], vp[0], aB);
                aB = fma2(sB2[2*jq+1], vp[1], aB);
            }
            float lo, hi;
            upk2(aA, lo, hi); oA[d] += lo + hi;
            upk2(aB, lo, hi); oB[d] += lo + hi;
        }
    }

    float lalo, lahi, lblo, lbhi;
    upk2(la2, lalo, lahi);
    upk2(lb2, lblo, lbhi);
    const float inva = 1.f / (lalo + lahi);
    const float invb = 1.f / (lblo + lbhi);
    float* outa = AO + (ta * PP + p) * CC + h * HD;
    float* outb = AO + (tb * PP + p) * CC + h * HD;
#pragma unroll
    for (int d4 = 0; d4 < HD / 4; d4++) {
        float4 va = make_float4(oA[d4*4] * inva, oA[d4*4+1] * inva,
                                oA[d4*4+2] * inva, oA[d4*4+3] * inva);
        float4 vb = make_float4(oB[d4*4] * invb, oB[d4*4+1] * invb,
                                oB[d4*4+2] * invb, oB[d4*4+3] * invb);
        *(float4*)(outa + d4 * 4) = va;
        *(float4*)(outb + d4 * 4) = vb;
    }
}

// ---------------------------------------------------------------------------
// Launch
// ---------------------------------------------------------------------------
extern "C" void kernel_launch(void* const* d_in, const int* in_sizes, int n_in,
                              void* d_out, int out_size) {
    const float* x      = (const float*)d_in[0];
    const float* cond   = (const float*)d_in[1];
    const float* mask   = (const float*)d_in[2];
    const float* lin_w  = (const float*)d_in[3];
    const float* lin_b  = (const float*)d_in[4];
    const float* qkv_w  = (const float*)d_in[5];
    const float* qkv_b  = (const float*)d_in[6];
    const float* rpb    = (const float*)d_in[7];
    const float* proj_w = (const float*)d_in[8];
    const float* proj_b = (const float*)d_in[9];
    float* out = (float*)d_out;

    float *pY, *pQKV, *pAO, *pWtLin, *pWtQkv, *pWtProj;
    cudaGetSymbolAddress((void**)&pY,      g_Y);
    cudaGetSymbolAddress((void**)&pQKV,    g_QKV);
    cudaGetSymbolAddress((void**)&pAO,     g_AO);
    cudaGetSymbolAddress((void**)&pWtLin,  g_WtLin);
    cudaGetSymbolAddress((void**)&pWtQkv,  g_WtQkv);
    cudaGetSymbolAddress((void**)&pWtProj, g_WtProj);

    // weight transposes
    transpose_w_kernel<<<(KCAT * CC + 255) / 256, 256>>>(pWtLin, lin_w, 131, KCAT, CC);
    transpose_w_kernel<<<(CC * 384 + 255) / 256, 256>>>(pWtQkv, qkv_w, CC, CC, 384);
    transpose_w_kernel<<<(CC * CC + 255) / 256, 256>>>(pWtProj, proj_w, CC, CC, CC);

    // fusion linear + relu -> Y  (concat fused into the A-tile load)
    gemm_kernel<0><<<dim3(1, M_ROWS / 128), 256>>>(x, CC, pWtLin, CC, lin_b, pY, KCAT,
                                                   cond, mask);

    for (int layer = 0; layer < 2; layer++) {
        // QKV projection (scatter into per-head layout, q pre-scaled)
        gemm_kernel<1><<<dim3(3, M_ROWS / 128), 256>>>(pY, CC, pWtQkv, 384, qkv_b, pQKV, CC,
                                                       nullptr, nullptr);
        // neighborhood attention -> AO (merged-head layout)
        attn_kernel<<<dim3(TT / BT, NH), dim3(PP, 2)>>>(pQKV, rpb, pAO);
        // output projection
        float* dst = (layer == 0) ? pY : out;
        gemm_kernel<2><<<dim3(1, M_ROWS / 128), 256>>>(pAO, CC, pWtProj, CC, proj_b, dst, CC,
                                                       nullptr, nullptr);
    }
}

// round 11
// speedup vs baseline: 1.3207x; 1.0027x over previous
#include <cuda_runtime.h>

// ---------------------------------------------------------------------------
// Problem constants
// ---------------------------------------------------------------------------
#define TT   256          // time frames (h)
#define PP   88           // pitches (w)
#define CC   128          // channels
#define NH   4            // heads
#define HD   32           // head dim
#define WIN  25           // neighborhood window
#define M_ROWS (TT*PP)    // 22528
#define KCAT 144          // padded concat K (128 + 2 + 1 -> pad to 144)
#define BT   4            // t-rows per attention block

#define QSCALE 0.17677669529663689f   // 32^-0.5
#define KVROW  90                     // K/V smem row stride (floats)
#define KVBUF  (HD*KVROW)             // one K or V plane (floats)

typedef unsigned long long ull;

// ---- f32x2 packed helpers (sm_103a FFMA2 is PTX-only) ----------------------
__device__ __forceinline__ ull pk2(float lo, float hi) {
    ull r; asm("mov.b64 %0,{%1,%2};" : "=l"(r) : "f"(lo), "f"(hi)); return r;
}
__device__ __forceinline__ ull dup2(float x) { return pk2(x, x); }
__device__ __forceinline__ ull fma2(ull a, ull b, ull c) {
    ull d; asm("fma.rn.f32x2 %0,%1,%2,%3;" : "=l"(d) : "l"(a), "l"(b), "l"(c)); return d;
}
__device__ __forceinline__ void upk2(ull v, float& lo, float& hi) {
    asm("mov.b64 {%0,%1},%2;" : "=f"(lo), "=f"(hi) : "l"(v));
}

// ---------------------------------------------------------------------------
// Scratch (static device globals -- no allocation allowed)
// ---------------------------------------------------------------------------
__device__ float g_Y[M_ROWS * CC];
__device__ float g_QKV[3 * NH * M_ROWS * HD];   // [i3][head][m][hd]
__device__ float g_AO[M_ROWS * CC];
__device__ float g_WtLin[KCAT * CC];            // [k][n]
__device__ float g_WtQkv[CC * 3 * CC];          // [k][n] n<384
__device__ float g_WtProj[CC * CC];             // [k][n]

// ---------------------------------------------------------------------------
// Prep kernel: transpose weights to [k][n], zero-pad k
// ---------------------------------------------------------------------------
__global__ void transpose_w_kernel(float* __restrict__ dst, const float* __restrict__ src,
                                   int Ksrc, int Kdst, int N) {
    int idx = blockIdx.x * 256 + threadIdx.x;
    if (idx >= Kdst * N) return;
    int k = idx / N, n = idx - k * N;
    dst[idx] = (k < Ksrc) ? src[n * Ksrc + k] : 0.f;
}

// ---------------------------------------------------------------------------
// Tiled SGEMM with f32x2 FMAs:  C[m][n] = sum_k A[m][k] * Bt[k][n] + bias[n]
// BM = 64, BN = 128, BK = 16, 256 threads, 4x8 micro-tile (held as 4x4 f32x2).
// BM=64 doubles the grid (352+ blocks) so 3-4 blocks/SM hide FMA latency
// (R10 ncu: occ 14.9%, issue 29% at BM=128 -- grid-starved).
// MODE 0: fusion  (A is the virtual concat [x | cond | mask | 0-pad], relu)
// MODE 1: qkv     (scatter into g_QKV layout, scale q by HD^-0.5)
// MODE 2: proj    (write row-major CC)
// ---------------------------------------------------------------------------
template <int MODE>
__global__ void __launch_bounds__(256) gemm_kernel(const float* __restrict__ A, int lda,
                                                   const float* __restrict__ Bt, int ldb,
                                                   const float* __restrict__ bias,
                                                   float* __restrict__ C, int K,
                                                   const float* __restrict__ cond,
                                                   const float* __restrict__ maskp) {
    __shared__ float As[16][68];    // [k][m], padded
    __shared__ float Bs[16][128];   // [k][n]

    const int m0 = blockIdx.y * 64;
    const int n0 = blockIdx.x * 128;
    const int tid = threadIdx.x;
    const int tx = tid & 15;
    const int ty = tid >> 4;

    ull acc2[4][4];
#pragma unroll
    for (int i = 0; i < 4; i++)
#pragma unroll
        for (int j = 0; j < 4; j++) acc2[i][j] = 0ull;

    for (int k0 = 0; k0 < K; k0 += 16) {
        // A tile: 64 rows x 16 k = 1 float4 per thread
        {
            int r  = tid >> 2;            // 0..63
            int c4 = (tid & 3) * 4;       // 0,4,8,12
            int row = m0 + r;
            float4 a4;
            if (MODE == 0) {
                if (k0 < CC) {
                    a4 = *(const float4*)(A + row * CC + k0 + c4);
                } else if (c4 == 0) {
                    a4 = make_float4(cond[row * 2], cond[row * 2 + 1], maskp[row], 0.f);
                } else {
                    a4 = make_float4(0.f, 0.f, 0.f, 0.f);
                }
            } else {
                a4 = *(const float4*)(A + row * lda + k0 + c4);
            }
            As[c4 + 0][r] = a4.x; As[c4 + 1][r] = a4.y;
            As[c4 + 2][r] = a4.z; As[c4 + 3][r] = a4.w;
        }
        // B tile: 16 x 128 = 2 float4 per thread
#pragma unroll
        for (int ii = 0; ii < 2; ii++) {
            int lin = tid + ii * 256;
            int rb = lin >> 5;            // 0..15
            int cb = (lin & 31) * 4;      // 0..124
            *(float4*)&Bs[rb][cb] = *(const float4*)(Bt + (k0 + rb) * ldb + n0 + cb);
        }
        __syncthreads();
#pragma unroll
        for (int kk = 0; kk < 16; kk++) {
            float a[4];
            *(float4*)&a[0] = *(const float4*)&As[kk][ty * 4];
            const ull* bp = (const ull*)&Bs[kk][tx * 8];
            ull b2[4] = { bp[0], bp[1], bp[2], bp[3] };
#pragma unroll
            for (int i = 0; i < 4; i++) {
                ull ad = dup2(a[i]);
#pragma unroll
                for (int j = 0; j < 4; j++)
                    acc2[i][j] = fma2(ad, b2[j], acc2[i][j]);
            }
        }
        __syncthreads();
    }

    // epilogue
#pragma unroll
    for (int i = 0; i < 4; i++) {
        int m = m0 + ty * 4 + i;
#pragma unroll
        for (int j4 = 0; j4 < 2; j4++) {
            int nbase = n0 + tx * 8 + j4 * 4;
            float vv[4];
            upk2(acc2[i][j4 * 2 + 0], vv[0], vv[1]);
            upk2(acc2[i][j4 * 2 + 1], vv[2], vv[3]);
#pragma unroll
            for (int j = 0; j < 4; j++) {
                float t = vv[j] + bias[nbase + j];
                if (MODE == 0) t = fmaxf(t, 0.f);
                if (MODE == 1 && nbase < 128) t *= QSCALE;
                vv[j] = t;
            }
            if (MODE == 1) {
                int i3   = nbase >> 7;
                int head = (nbase >> 5) & 3;
                int hd   = nbase & 31;
                *(float4*)&C[((i3 * NH + head) * M_ROWS + m) * HD + hd] = *(float4*)vv;
            } else {
                *(float4*)&C[m * CC + nbase] = *(float4*)vv;
            }
        }
    }
}

// ---------------------------------------------------------------------------
// Neighborhood attention: one head per block, BT=4 t-rows, 176 threads, each
// thread owns 2 t-packed queries (ta=t0+ty, tb=ta+2) -- the proven R8 core
// (991us). NEW: double-buffered K/V smem planes -> ONE __syncthreads per key
// row (was 2). Producers store row tr+1 into buf^1 while this iter computes
// from buf; the single end-of-iter bar makes it visible. Halves barrier count
// and removes the bar-to-bar pipeline collapse under fma/LDS co-saturation.
// Max-free softmax (scores tiny: 0.02-scaled weights). Window slab [x0,x0+25]
// packed as 13 f32x2 pairs, K/V via LDS.64 shared by both queries.
// ---------------------------------------------------------------------------
__global__ void __launch_bounds__(176, 2) attn_kernel(const float* __restrict__ QKVbuf,
                                                      const float* __restrict__ rpb,
                                                      float* __restrict__ AO) {
    extern __shared__ float dyn[];       // 2 buffers x (K plane + V plane)
    __shared__ float Rpb[49 * 49];

    const int h  = blockIdx.y;
    const int t0 = blockIdx.x * BT;
    const int p  = threadIdx.x;          // 0..87
    const int ty = threadIdx.y;          // 0..1
    const int tid = ty * PP + p;         // 0..175

    const float* Qg = QKVbuf;
    const float* Kg = QKVbuf + NH * M_ROWS * HD;
    const float* Vg = QKVbuf + 2 * NH * M_ROWS * HD;

    for (int i = tid; i < 49 * 49; i += 176) Rpb[i] = rpb[h * 49 * 49 + i];

    const int ta  = t0 + ty;             // query rows: ta, ta+2
    const int tb  = ta + 2;
    const int sa  = min(max(ta - 12, 0), TT - WIN);
    const int sb  = min(max(tb - 12, 0), TT - WIN);
    const int pw0 = min(max(p - 12, 0), PP - WIN);
    const int x0  = pw0 & ~1;            // even slab base
    const bool ok0  = (pw0 == x0);       // slot 0 valid iff slab unshifted
    const bool ok25 = (pw0 != x0);       // slot 25 valid iff slab shifted

    const float4* qa_ptr = (const float4*)(Qg + ((h * TT + ta) * PP + p) * HD);
    const float4* qb_ptr = (const float4*)(Qg + ((h * TT + tb) * PP + p) * HD);

    float oA[HD], oB[HD];
#pragma unroll
    for (int d = 0; d < HD; d++) { oA[d] = 0.f; oB[d] = 0.f; }
    float la = 0.f, lb = 0.f;

    const int rlo = min(max(t0 - 12, 0), TT - WIN);
    const int rhi = min(max(t0 + BT - 1 - 12, 0), TT - WIN) + WIN - 1;

    // per-thread chunk coordinates for the cooperative K/V row load
    int pc_[4], dq_[4];
#pragma unroll
    for (int it = 0; it < 4; it++) {
        int e = tid + it * 176;          // 0..703 (= PP*8)
        pc_[it] = e >> 3;
        dq_[it] = (e & 7) * 4;
    }

    // ---- prologue: load row rlo, store to buffer 0, one bar
    float4 k4s[4], v4s[4];
    {
        const float* kb = Kg + (h * TT + rlo) * PP * HD;
        const float* vb = Vg + (h * TT + rlo) * PP * HD;
#pragma unroll
        for (int it = 0; it < 4; it++) {
            k4s[it] = *(const float4*)(kb + pc_[it] * HD + dq_[it]);
            v4s[it] = *(const float4*)(vb + pc_[it] * HD + dq_[it]);
        }
        float* K0 = dyn;
        float* V0 = dyn + KVBUF;
#pragma unroll
        for (int it = 0; it < 4; it++) {
            int pc = pc_[it], dq = dq_[it];
            K0[(dq + 0) * KVROW + pc] = k4s[it].x; K0[(dq + 1) * KVROW + pc] = k4s[it].y;
            K0[(dq + 2) * KVROW + pc] = k4s[it].z; K0[(dq + 3) * KVROW + pc] = k4s[it].w;
            V0[(dq + 0) * KVROW + pc] = v4s[it].x; V0[(dq + 1) * KVROW + pc] = v4s[it].y;
            V0[(dq + 2) * KVROW + pc] = v4s[it].z; V0[(dq + 3) * KVROW + pc] = v4s[it].w;
        }
    }
    __syncthreads();

    for (int tr = rlo; tr <= rhi; tr++) {
        const int cur = (tr - rlo) & 1;
        const float* Kc = dyn + cur * (2 * KVBUF);
        const float* Vc = Kc + KVBUF;
        float* Kn = dyn + (cur ^ 1) * (2 * KVBUF);
        float* Vn = Kn + KVBUF;

        // issue LDGs for row tr+1 early -- latency hides behind compute
        const bool more = (tr < rhi);
        if (more) {
            const float* kb = Kg + (h * TT + tr + 1) * PP * HD;
            const float* vb = Vg + (h * TT + tr + 1) * PP * HD;
#pragma unroll
            for (int it = 0; it < 4; it++) {
                k4s[it] = *(const float4*)(kb + pc_[it] * HD + dq_[it]);
                v4s[it] = *(const float4*)(vb + pc_[it] * HD + dq_[it]);
            }
        }

        const bool actA = (tr >= sa) && (tr < sa + WIN);
        const bool actB = (tr >= sb) && (tr < sb + WIN);
        if (actA || actB) {
            // ---- scores: sX2[jp] = (q . K[:, x0+2jp], q . K[:, x0+2jp+1])
            ull sA2[13], sB2[13];
#pragma unroll
            for (int jp = 0; jp < 13; jp++) { sA2[jp] = 0ull; sB2[jp] = 0ull; }

#pragma unroll
            for (int d4 = 0; d4 < HD / 4; d4++) {
                float4 qa4 = qa_ptr[d4];
                float4 qb4 = qb_ptr[d4];
                const float* qaf = (const float*)&qa4;
                const float* qbf = (const float*)&qb4;
#pragma unroll
                for (int dd = 0; dd < 4; dd++) {
                    const int d = d4 * 4 + dd;
                    ull qaD = dup2(qaf[dd]);
                    ull qbD = dup2(qbf[dd]);
                    const ull* kr = (const ull*)&Kc[d * KVROW + x0];
#pragma unroll
                    for (int jp = 0; jp < 13; jp++) {
                        ull k2 = kr[jp];
                        sA2[jp] = fma2(qaD, k2, sA2[jp]);
                        sB2[jp] = fma2(qbD, k2, sB2[jp]);
                    }
                }
            }

            // ---- + rpb, exp (max-free), accumulate l; repack probs into sX2
            const int baseA = (tr - ta + 24) * 49 + (x0 - p + 24);
            const int baseB = (tr - tb + 24) * 49 + (x0 - p + 24);
#pragma unroll
            for (int jp = 0; jp < 13; jp++) {
                const int s0 = 2 * jp, s1 = 2 * jp + 1;
                const bool v0 = (s0 != 0 || ok0);
                const bool v1 = (s1 != 25 || ok25);
                float f0, f1, g0, g1;
                upk2(sA2[jp], f0, f1);
                g0 = (actA && v0) ? __expf(f0 + Rpb[baseA + s0]) : 0.f;
                g1 = (actA && v1) ? __expf(f1 + Rpb[baseA + s1]) : 0.f;
                la += g0 + g1;
                sA2[jp] = pk2(g0, g1);
                upk2(sB2[jp], f0, f1);
                g0 = (actB && v0) ? __expf(f0 + Rpb[baseB + s0]) : 0.f;
                g1 = (actB && v1) ? __expf(f1 + Rpb[baseB + s1]) : 0.f;
                lb += g0 + g1;
                sB2[jp] = pk2(g0, g1);
            }

            // ---- AV accumulate (V LDS.64 shared by both queries)
#pragma unroll
            for (int d = 0; d < HD; d++) {
                const ull* vr = (const ull*)&Vc[d * KVROW + x0];
                ull aA = 0ull, aB = 0ull;
#pragma unroll
                for (int jp = 0; jp < 13; jp++) {
                    ull v2 = vr[jp];
                    aA = fma2(sA2[jp], v2, aA);
                    aB = fma2(sB2[jp], v2, aB);
                }
                float lo, hi;
                upk2(aA, lo, hi); oA[d] += lo + hi;
                upk2(aB, lo, hi); oB[d] += lo + hi;
            }
        }

        // commit staged row tr+1 into the other buffer (no reader conflicts)
        if (more) {
#pragma unroll
            for (int it = 0; it < 4; it++) {
                int pc = pc_[it], dq = dq_[it];
                Kn[(dq + 0) * KVROW + pc] = k4s[it].x; Kn[(dq + 1) * KVROW + pc] = k4s[it].y;
                Kn[(dq + 2) * KVROW + pc] = k4s[it].z; Kn[(dq + 3) * KVROW + pc] = k4s[it].w;
                Vn[(dq + 0) * KVROW + pc] = v4s[it].x; Vn[(dq + 1) * KVROW + pc] = v4s[it].y;
                Vn[(dq + 2) * KVROW + pc] = v4s[it].z; Vn[(dq + 3) * KVROW + pc] = v4s[it].w;
            }
        }
        __syncthreads();                 // single bar per iteration
    }

    const float inva = 1.f / la;
    const float invb = 1.f / lb;
    float* outa = AO + (ta * PP + p) * CC + h * HD;
    float* outb = AO + (tb * PP + p) * CC + h * HD;
#pragma unroll
    for (int d4 = 0; d4 < HD / 4; d4++) {
        float4 va = make_float4(oA[d4*4] * inva, oA[d4*4+1] * inva,
                                oA[d4*4+2] * inva, oA[d4*4+3] * inva);
        float4 vb = make_float4(oB[d4*4] * invb, oB[d4*4+1] * invb,
                                oB[d4*4+2] * invb, oB[d4*4+3] * invb);
        *(float4*)(outa + d4 * 4) = va;
        *(float4*)(outb + d4 * 4) = vb;
    }
}

// ---------------------------------------------------------------------------
// Launch
// ---------------------------------------------------------------------------
extern "C" void kernel_launch(void* const* d_in, const int* in_sizes, int n_in,
                              void* d_out, int out_size) {
    const float* x      = (const float*)d_in[0];
    const float* cond   = (const float*)d_in[1];
    const float* mask   = (const float*)d_in[2];
    const float* lin_w  = (const float*)d_in[3];
    const float* lin_b  = (const float*)d_in[4];
    const float* qkv_w  = (const float*)d_in[5];
    const float* qkv_b  = (const float*)d_in[6];
    const float* rpb    = (const float*)d_in[7];
    const float* proj_w = (const float*)d_in[8];
    const float* proj_b = (const float*)d_in[9];
    float* out = (float*)d_out;

    float *pY, *pQKV, *pAO, *pWtLin, *pWtQkv, *pWtProj;
    cudaGetSymbolAddress((void**)&pY,      g_Y);
    cudaGetSymbolAddress((void**)&pQKV,    g_QKV);
    cudaGetSymbolAddress((void**)&pAO,     g_AO);
    cudaGetSymbolAddress((void**)&pWtLin,  g_WtLin);
    cudaGetSymbolAddress((void**)&pWtQkv,  g_WtQkv);
    cudaGetSymbolAddress((void**)&pWtProj, g_WtProj);

    const int kv_smem = 2 * 2 * KVBUF * (int)sizeof(float);   // 46080 B
    cudaFuncSetAttribute(attn_kernel, cudaFuncAttributeMaxDynamicSharedMemorySize, kv_smem);

    // weight transposes
    transpose_w_kernel<<<(KCAT * CC + 255) / 256, 256>>>(pWtLin, lin_w, 131, KCAT, CC);
    transpose_w_kernel<<<(CC * 384 + 255) / 256, 256>>>(pWtQkv, qkv_w, CC, CC, 384);
    transpose_w_kernel<<<(CC * CC + 255) / 256, 256>>>(pWtProj, proj_w, CC, CC, CC);

    // fusion linear + relu -> Y  (concat fused into the A-tile load)
    gemm_kernel<0><<<dim3(1, M_ROWS / 64), 256>>>(x, CC, pWtLin, CC, lin_b, pY, KCAT,
                                                  cond, mask);

    for (int layer = 0; layer < 2; layer++) {
        // QKV projection (scatter into per-head layout, q pre-scaled)
        gemm_kernel<1><<<dim3(3, M_ROWS / 64), 256>>>(pY, CC, pWtQkv, 384, qkv_b, pQKV, CC,
                                                      nullptr, nullptr);
        // neighborhood attention -> AO (merged-head layout)
        attn_kernel<<<dim3(TT / BT, NH), dim3(PP, 2), kv_smem>>>(pQKV, rpb, pAO);
        // output projection
        float* dst = (layer == 0) ? pY : out;
        gemm_kernel<2><<<dim3(1, M_ROWS / 64), 256>>>(pAO, CC, pWtProj, CC, proj_b, dst, CC,
                                                      nullptr, nullptr);
    }
}

// round 14
// speedup vs baseline: 1.3930x; 1.0547x over previous
#include <cuda_runtime.h>

// ---------------------------------------------------------------------------
// Problem constants
// ---------------------------------------------------------------------------
#define TT   256          // time frames (h)
#define PP   88           // pitches (w)
#define CC   128          // channels
#define NH   4            // heads
#define HD   32           // head dim
#define WIN  25           // neighborhood window
#define M_ROWS (TT*PP)    // 22528
#define KCAT 144          // padded concat K (128 + 2 + 1 -> pad to 144)
#define BT   4            // t-rows per attention block

#define QSCALE 0.17677669529663689f   // 32^-0.5

typedef unsigned long long ull;

// ---- f32x2 packed helpers (sm_103a FFMA2 is PTX-only) ----------------------
__device__ __forceinline__ ull pk2(float lo, float hi) {
    ull r; asm("mov.b64 %0,{%1,%2};" : "=l"(r) : "f"(lo), "f"(hi)); return r;
}
__device__ __forceinline__ ull dup2(float x) { return pk2(x, x); }
__device__ __forceinline__ ull fma2(ull a, ull b, ull c) {
    ull d; asm("fma.rn.f32x2 %0,%1,%2,%3;" : "=l"(d) : "l"(a), "l"(b), "l"(c)); return d;
}
__device__ __forceinline__ void upk2(ull v, float& lo, float& hi) {
    asm("mov.b64 {%0,%1},%2;" : "=f"(lo), "=f"(hi) : "l"(v));
}

// ---------------------------------------------------------------------------
// Scratch (static device globals -- no allocation allowed)
// ---------------------------------------------------------------------------
__device__ float g_Y[M_ROWS * CC];
__device__ float g_QKV[3 * NH * M_ROWS * HD];   // [i3][head][m][hd]
__device__ float g_AO[M_ROWS * CC];
__device__ float g_WtLin[KCAT * CC];            // [k][n]
__device__ float g_WtQkv[CC * 3 * CC];          // [k][n] n<384
__device__ float g_WtProj[CC * CC];             // [k][n]

// ---------------------------------------------------------------------------
// Prep kernel: all three weight transposes in one launch.
// work item space: lin = [0, KCAT*CC + CC*384 + CC*CC)
// ---------------------------------------------------------------------------
__global__ void transpose_all_kernel(const float* __restrict__ lin_w,
                                     const float* __restrict__ qkv_w,
                                     const float* __restrict__ proj_w) {
    int idx = blockIdx.x * 256 + threadIdx.x;
    const int n1 = KCAT * CC;            // WtLin
    const int n2 = n1 + CC * 384;        // WtQkv
    const int n3 = n2 + CC * CC;         // WtProj
    if (idx < n1) {
        int k = idx / CC, n = idx - k * CC;
        g_WtLin[idx] = (k < 131) ? lin_w[n * 131 + k] : 0.f;
    } else if (idx < n2) {
        int j = idx - n1;
        int k = j / 384, n = j - k * 384;
        g_WtQkv[j] = qkv_w[n * CC + k];
    } else if (idx < n3) {
        int j = idx - n2;
        int k = j / CC, n = j - k * CC;
        g_WtProj[j] = proj_w[n * CC + k];
    }
}

// ---------------------------------------------------------------------------
// Tiled SGEMM with f32x2 FMAs:  C[m][n] = sum_k A[m][k] * Bt[k][n] + bias[n]
// BM = BN = 128, BK = 16, 256 threads, 8x8 micro-tile (held as 8x4 f32x2).
// NEW: double-buffered smem tiles + register-staged global prefetch -- the
// LDG for k-tile t+1 issues before computing tile t, and a single bar/iter
// publishes it. Hides the ~250cyc L2 latency that was fully exposed between
// the two bars of every k-step (ncu: issue 29%, fma 28% at occ 15%).
// MODE 0: fusion  (A is the virtual concat [x | cond | mask | 0-pad], relu)
// MODE 1: qkv     (scatter into g_QKV layout, scale q by HD^-0.5)
// MODE 2: proj    (write row-major CC)
// ---------------------------------------------------------------------------
template <int MODE>
__global__ void __launch_bounds__(256) gemm_kernel(const float* __restrict__ A, int lda,
                                                   const float* __restrict__ Bt, int ldb,
                                                   const float* __restrict__ bias,
                                                   float* __restrict__ C, int K,
                                                   const float* __restrict__ cond,
                                                   const float* __restrict__ maskp) {
    __shared__ float As[2][16][132];   // [buf][k][m], padded
    __shared__ float Bs[2][16][128];   // [buf][k][n]

    const int m0 = blockIdx.y * 128;
    const int n0 = blockIdx.x * 128;
    const int tid = threadIdx.x;
    const int tx = tid & 15;
    const int ty = tid >> 4;

    // loader lane mapping (each thread: 2 A-float4 + 2 B-float4 per tile)
    int ar_[2], ac_[2], br_[2], bc_[2];
#pragma unroll
    for (int ii = 0; ii < 2; ii++) {
        int lin = tid + ii * 256;
        ar_[ii] = lin >> 2;              // 0..127
        ac_[ii] = (lin & 3) * 4;         // 0,4,8,12
        br_[ii] = lin >> 5;              // 0..15
        bc_[ii] = (lin & 31) * 4;        // 0..124
    }

    float4 a4s[2], b4s[2];
    auto load_tile = [&](int k0) {
#pragma unroll
        for (int ii = 0; ii < 2; ii++) {
            int row = m0 + ar_[ii];
            int c4  = ac_[ii];
            if (MODE == 0) {
                if (k0 < CC) {
                    a4s[ii] = *(const float4*)(A + row * CC + k0 + c4);
                } else if (c4 == 0) {
                    a4s[ii] = make_float4(cond[row * 2], cond[row * 2 + 1], maskp[row], 0.f);
                } else {
                    a4s[ii] = make_float4(0.f, 0.f, 0.f, 0.f);
                }
            } else {
                a4s[ii] = *(const float4*)(A + row * lda + k0 + c4);
            }
            b4s[ii] = *(const float4*)(Bt + (k0 + br_[ii]) * ldb + n0 + bc_[ii]);
        }
    };
    auto store_tile = [&](int buf) {
#pragma unroll
        for (int ii = 0; ii < 2; ii++) {
            int r = ar_[ii], c4 = ac_[ii];
            As[buf][c4 + 0][r] = a4s[ii].x; As[buf][c4 + 1][r] = a4s[ii].y;
            As[buf][c4 + 2][r] = a4s[ii].z; As[buf][c4 + 3][r] = a4s[ii].w;
            *(float4*)&Bs[buf][br_[ii]][bc_[ii]] = b4s[ii];
        }
    };

    ull acc2[8][4];
#pragma unroll
    for (int i = 0; i < 8; i++)
#pragma unroll
        for (int j = 0; j < 4; j++) acc2[i][j] = 0ull;

    const int nk = K / 16;
    load_tile(0);
    store_tile(0);
    __syncthreads();

    for (int kt = 0; kt < nk; kt++) {
        const int cur = kt & 1;
        const bool more = (kt + 1 < nk);
        if (more) load_tile((kt + 1) * 16);   // LDG overlaps compute below

#pragma unroll
        for (int kk = 0; kk < 16; kk++) {
            float a[8];
            *(float4*)&a[0] = *(const float4*)&As[cur][kk][ty * 8];
            *(float4*)&a[4] = *(const float4*)&As[cur][kk][ty * 8 + 4];
            const ull* bp = (const ull*)&Bs[cur][kk][tx * 8];
            ull b2[4] = { bp[0], bp[1], bp[2], bp[3] };
#pragma unroll
            for (int i = 0; i < 8; i++) {
                ull ad = dup2(a[i]);
#pragma unroll
                for (int j = 0; j < 4; j++)
                    acc2[i][j] = fma2(ad, b2[j], acc2[i][j]);
            }
        }
        if (more) store_tile(cur ^ 1);        // writes the other buffer
        __syncthreads();                      // single bar per k-tile
    }

    // epilogue
#pragma unroll
    for (int i = 0; i < 8; i++) {
        int m = m0 + ty * 8 + i;
#pragma unroll
        for (int j4 = 0; j4 < 2; j4++) {
            int nbase = n0 + tx * 8 + j4 * 4;
            float vv[4];
            upk2(acc2[i][j4 * 2 + 0], vv[0], vv[1]);
            upk2(acc2[i][j4 * 2 + 1], vv[2], vv[3]);
#pragma unroll
            for (int j = 0; j < 4; j++) {
                float t = vv[j] + bias[nbase + j];
                if (MODE == 0) t = fmaxf(t, 0.f);
                if (MODE == 1 && nbase < 128) t *= QSCALE;
                vv[j] = t;
            }
            if (MODE == 1) {
                int i3   = nbase >> 7;
                int head = (nbase >> 5) & 3;
                int hd   = nbase & 31;
                *(float4*)&C[((i3 * NH + head) * M_ROWS + m) * HD + hd] = *(float4*)vv;
            } else {
                *(float4*)&C[m * CC + nbase] = *(float4*)vv;
            }
        }
    }
}

// ---------------------------------------------------------------------------
// Neighborhood attention -- byte-identical to the proven 991us R8 kernel.
// One head per block, BT=4 t-rows, 2 t-packed queries per thread, max-free
// softmax, 13 f32x2 window pairs, software-pipelined K/V row LDGs.
// ---------------------------------------------------------------------------
__global__ void __launch_bounds__(176, 2) attn_kernel(const float* __restrict__ QKVbuf,
                                                      const float* __restrict__ rpb,
                                                      float* __restrict__ AO) {
    __shared__ float Ksh[HD][90];   // [d][p], 8B-aligned rows, conflict-free
    __shared__ float Vsh[HD][90];
    __shared__ float Rpb[49 * 49];

    const int h  = blockIdx.y;
    const int t0 = blockIdx.x * BT;
    const int p  = threadIdx.x;          // 0..87
    const int ty = threadIdx.y;          // 0..1
    const int tid = ty * PP + p;         // 0..175

    const float* Qg = QKVbuf;
    const float* Kg = QKVbuf + NH * M_ROWS * HD;
    const float* Vg = QKVbuf + 2 * NH * M_ROWS * HD;

    for (int i = tid; i < 49 * 49; i += 176) Rpb[i] = rpb[h * 49 * 49 + i];

    const int ta  = t0 + ty;             // query rows: ta, ta+2
    const int tb  = ta + 2;
    const int sa  = min(max(ta - 12, 0), TT - WIN);
    const int sb  = min(max(tb - 12, 0), TT - WIN);
    const int pw0 = min(max(p - 12, 0), PP - WIN);
    const int x0  = pw0 & ~1;            // even slab base
    const bool ok0  = (pw0 == x0);       // slot 0 valid iff slab unshifted
    const bool ok25 = (pw0 != x0);       // slot 25 valid iff slab shifted

    const float4* qa_ptr = (const float4*)(Qg + ((h * TT + ta) * PP + p) * HD);
    const float4* qb_ptr = (const float4*)(Qg + ((h * TT + tb) * PP + p) * HD);

    float oA[HD], oB[HD];
#pragma unroll
    for (int d = 0; d < HD; d++) { oA[d] = 0.f; oB[d] = 0.f; }
    float la = 0.f, lb = 0.f;

    const int rlo = min(max(t0 - 12, 0), TT - WIN);
    const int rhi = min(max(t0 + BT - 1 - 12, 0), TT - WIN) + WIN - 1;

    // per-thread chunk coordinates for the cooperative K/V row load
    int pc_[4], dq_[4];
#pragma unroll
    for (int it = 0; it < 4; it++) {
        int e = tid + it * 176;          // 0..703 (= PP*8)
        pc_[it] = e >> 3;
        dq_[it] = (e & 7) * 4;
    }

    // ---- prologue: stage row rlo in registers
    float4 k4s[4], v4s[4];
    {
        const float* kb = Kg + (h * TT + rlo) * PP * HD;
        const float* vb = Vg + (h * TT + rlo) * PP * HD;
#pragma unroll
        for (int it = 0; it < 4; it++) {
            k4s[it] = *(const float4*)(kb + pc_[it] * HD + dq_[it]);
            v4s[it] = *(const float4*)(vb + pc_[it] * HD + dq_[it]);
        }
    }

    for (int tr = rlo; tr <= rhi; tr++) {
        __syncthreads();                 // prior compute done reading smem
        // commit staged row tr (transposed to [d][p])
#pragma unroll
        for (int it = 0; it < 4; it++) {
            int pc = pc_[it], dq = dq_[it];
            Ksh[dq + 0][pc] = k4s[it].x; Ksh[dq + 1][pc] = k4s[it].y;
            Ksh[dq + 2][pc] = k4s[it].z; Ksh[dq + 3][pc] = k4s[it].w;
            Vsh[dq + 0][pc] = v4s[it].x; Vsh[dq + 1][pc] = v4s[it].y;
            Vsh[dq + 2][pc] = v4s[it].z; Vsh[dq + 3][pc] = v4s[it].w;
        }
        // issue LDGs for row tr+1 -- latency hides behind this row's compute
        if (tr < rhi) {
            const float* kb = Kg + (h * TT + tr + 1) * PP * HD;
            const float* vb = Vg + (h * TT + tr + 1) * PP * HD;
#pragma unroll
            for (int it = 0; it < 4; it++) {
                k4s[it] = *(const float4*)(kb + pc_[it] * HD + dq_[it]);
                v4s[it] = *(const float4*)(vb + pc_[it] * HD + dq_[it]);
            }
        }
        __syncthreads();                 // smem row tr visible

        const bool actA = (tr >= sa) && (tr < sa + WIN);
        const bool actB = (tr >= sb) && (tr < sb + WIN);
        if (!(actA || actB)) continue;

        // ---- scores: sX2[jp] = (q . K[:, x0+2jp], q . K[:, x0+2jp+1])
        ull sA2[13], sB2[13];
#pragma unroll
        for (int jp = 0; jp < 13; jp++) { sA2[jp] = 0ull; sB2[jp] = 0ull; }

#pragma unroll
        for (int d4 = 0; d4 < HD / 4; d4++) {
            float4 qa4 = qa_ptr[d4];
            float4 qb4 = qb_ptr[d4];
            const float* qaf = (const float*)&qa4;
            const float* qbf = (const float*)&qb4;
#pragma unroll
            for (int dd = 0; dd < 4; dd++) {
                const int d = d4 * 4 + dd;
                ull qaD = dup2(qaf[dd]);
                ull qbD = dup2(qbf[dd]);
                const ull* kr = (const ull*)&Ksh[d][x0];
#pragma unroll
                for (int jp = 0; jp < 13; jp++) {
                    ull k2 = kr[jp];
                    sA2[jp] = fma2(qaD, k2, sA2[jp]);
                    sB2[jp] = fma2(qbD, k2, sB2[jp]);
                }
            }
        }

        // ---- + rpb, exp (max-free), accumulate l; repack probs into sX2
        const int baseA = (tr - ta + 24) * 49 + (x0 - p + 24);
        const int baseB = (tr - tb + 24) * 49 + (x0 - p + 24);
#pragma unroll
        for (int jp = 0; jp < 13; jp++) {
            const int s0 = 2 * jp, s1 = 2 * jp + 1;
            const bool v0 = (s0 != 0 || ok0);
            const bool v1 = (s1 != 25 || ok25);
            float f0, f1, g0, g1;
            upk2(sA2[jp], f0, f1);
            g0 = (actA && v0) ? __expf(f0 + Rpb[baseA + s0]) : 0.f;
            g1 = (actA && v1) ? __expf(f1 + Rpb[baseA + s1]) : 0.f;
            la += g0 + g1;
            sA2[jp] = pk2(g0, g1);
            upk2(sB2[jp], f0, f1);
            g0 = (actB && v0) ? __expf(f0 + Rpb[baseB + s0]) : 0.f;
            g1 = (actB && v1) ? __expf(f1 + Rpb[baseB + s1]) : 0.f;
            lb += g0 + g1;
            sB2[jp] = pk2(g0, g1);
        }

        // ---- AV accumulate (V LDS.64 shared by both queries)
#pragma unroll
        for (int d = 0; d < HD; d++) {
            const ull* vr = (const ull*)&Vsh[d][x0];
            ull aA = 0ull, aB = 0ull;
#pragma unroll
            for (int jp = 0; jp < 13; jp++) {
                ull v2 = vr[jp];
                aA = fma2(sA2[jp], v2, aA);
                aB = fma2(sB2[jp], v2, aB);
            }
            float lo, hi;
            upk2(aA, lo, hi); oA[d] += lo + hi;
            upk2(aB, lo, hi); oB[d] += lo + hi;
        }
    }

    const float inva = 1.f / la;
    const float invb = 1.f / lb;
    float* outa = AO + (ta * PP + p) * CC + h * HD;
    float* outb = AO + (tb * PP + p) * CC + h * HD;
#pragma unroll
    for (int d4 = 0; d4 < HD / 4; d4++) {
        float4 va = make_float4(oA[d4*4] * inva, oA[d4*4+1] * inva,
                                oA[d4*4+2] * inva, oA[d4*4+3] * inva);
        float4 vb = make_float4(oB[d4*4] * invb, oB[d4*4+1] * invb,
                                oB[d4*4+2] * invb, oB[d4*4+3] * invb);
        *(float4*)(outa + d4 * 4) = va;
        *(float4*)(outb + d4 * 4) = vb;
    }
}

// ---------------------------------------------------------------------------
// Launch
// ---------------------------------------------------------------------------
extern "C" void kernel_launch(void* const* d_in, const int* in_sizes, int n_in,
                              void* d_out, int out_size) {
    const float* x      = (const float*)d_in[0];
    const float* cond   = (const float*)d_in[1];
    const float* mask   = (const float*)d_in[2];
    const float* lin_w  = (const float*)d_in[3];
    const float* lin_b  = (const float*)d_in[4];
    const float* qkv_w  = (const float*)d_in[5];
    const float* qkv_b  = (const float*)d_in[6];
    const float* rpb    = (const float*)d_in[7];
    const float* proj_w = (const float*)d_in[8];
    const float* proj_b = (const float*)d_in[9];
    float* out = (float*)d_out;

    float *pY, *pQKV, *pAO, *pWtLin, *pWtQkv, *pWtProj;
    cudaGetSymbolAddress((void**)&pY,      g_Y);
    cudaGetSymbolAddress((void**)&pQKV,    g_QKV);
    cudaGetSymbolAddress((void**)&pAO,     g_AO);
    cudaGetSymbolAddress((void**)&pWtLin,  g_WtLin);
    cudaGetSymbolAddress((void**)&pWtQkv,  g_WtQkv);
    cudaGetSymbolAddress((void**)&pWtProj, g_WtProj);

    // all weight transposes in one launch
    const int tw_items = KCAT * CC + CC * 384 + CC * CC;
    transpose_all_kernel<<<(tw_items + 255) / 256, 256>>>(lin_w, qkv_w, proj_w);

    // fusion linear + relu -> Y  (concat fused into the A-tile load)
    gemm_kernel<0><<<dim3(1, M_ROWS / 128), 256>>>(x, CC, pWtLin, CC, lin_b, pY, KCAT,
                                                   cond, mask);

    for (int layer = 0; layer < 2; layer++) {
        // QKV projection (scatter into per-head layout, q pre-scaled)
        gemm_kernel<1><<<dim3(3, M_ROWS / 128), 256>>>(pY, CC, pWtQkv, 384, qkv_b, pQKV, CC,
                                                       nullptr, nullptr);
        // neighborhood attention -> AO (merged-head layout)
        attn_kernel<<<dim3(TT / BT, NH), dim3(PP, 2)>>>(pQKV, rpb, pAO);
        // output projection
        float* dst = (layer == 0) ? pY : out;
        gemm_kernel<2><<<dim3(1, M_ROWS / 128), 256>>>(pAO, CC, pWtProj, CC, proj_b, dst, CC,
                                                       nullptr, nullptr);
    }
}